// round 10
// baseline (speedup 1.0000x reference)
#include <cuda_runtime.h>

// LSTMForecastModel: B=4096, T=128, OUT=64, H=200.
// R9: f32x2 FMA with ROW-pairing (h pairs come free from LDS.128), weights
// pre-DUPLICATED in global so the packed multiplier loads with zero MOVs.
// MCTA=28 -> 147 CTAs fills 147/148 SMs (was 128). Parallel linear head.

#define BATCH  4096
#define TLEN   128
#define OUTLEN 64
#define HID    200
#define MCTA   28
#define NTHR   700      // 100 unit-pairs (tu) * 7 row-blocks (ty, 4 rows each)
#define NBLK   147      // ceil(4096/28)
#define WROW   1600     // dup'd floats per k: 100 tu * 16
#define WSZ    (HID * WROW)   // 320000 per matrix

typedef unsigned long long u64;

// Dup'd weights: [k*1600 + tu*16 + c*4 + e], chunks per (k,tu):
//   c0=(iA,iA,fA,fA) c1=(gA,gA,oA,oA) c2=(iB,iB,fB,fB) c3=(gB,gB,oB,oB)
// where uA=tu, uB=tu+100. Matrices: 0=enc_Whh0 1=enc_Wih1 2=enc_Whh1
//                                   3=dec_Whh0 4=dec_Wih1 5=dec_Whh1
__device__ float g_W[6][WSZ];
// Dup'd vectors, same 16-float-per-tu layout:
// 0=enc_Wih0 1=enc_b0 2=enc_b1 3=dec_Wih0 4=dec_b0 5=dec_b1
__device__ float g_v[6][WROW];

__global__ void prep_kernel(const float* __restrict__ eWhh0, const float* __restrict__ eWih1,
                            const float* __restrict__ eWhh1, const float* __restrict__ dWhh0,
                            const float* __restrict__ dWih1, const float* __restrict__ dWhh1,
                            const float* __restrict__ eWih0, const float* __restrict__ eb0,
                            const float* __restrict__ eb1,  const float* __restrict__ dWih0,
                            const float* __restrict__ db0,  const float* __restrict__ db1)
{
    int i = blockIdx.x * blockDim.x + threadIdx.x;
    if (i < WSZ) {
        int k  = i / WROW;
        int r  = i - k * WROW;
        int tu = r >> 4;
        int q  = r & 15;
        int c  = q >> 2;
        int e  = q & 3;
        int unit = tu + ((c & 2) ? 100 : 0);
        int g    = ((c & 1) << 1) | (e >> 1);     // i,f,g,o order
        int s = (g * HID + unit) * HID + k;
        g_W[0][i] = eWhh0[s];
        g_W[1][i] = eWih1[s];
        g_W[2][i] = eWhh1[s];
        g_W[3][i] = dWhh0[s];
        g_W[4][i] = dWih1[s];
        g_W[5][i] = dWhh1[s];
    }
    if (i < WROW) {
        int tu = i >> 4, q = i & 15, c = q >> 2, e = q & 3;
        int unit = tu + ((c & 2) ? 100 : 0);
        int g    = ((c & 1) << 1) | (e >> 1);
        int s = g * HID + unit;
        g_v[0][i] = eWih0[s];
        g_v[1][i] = eb0[s];
        g_v[2][i] = eb1[s];
        g_v[3][i] = dWih0[s];
        g_v[4][i] = db0[s];
        g_v[5][i] = db1[s];
    }
}

// ---- packed f32x2 primitives ----
__device__ __forceinline__ void fma2(u64& d, u64 a, u64 b) {
    asm("fma.rn.f32x2 %0, %1, %2, %0;" : "+l"(d) : "l"(a), "l"(b));
}
__device__ __forceinline__ u64 pair_of(float lo, float hi) {
    u64 r;
    asm("mov.b64 %0, {%1, %2};" : "=l"(r) : "f"(lo), "f"(hi));
    return r;
}
__device__ __forceinline__ float2 unpk(u64 v) {
    float lo, hi;
    asm("mov.b64 {%0, %1}, %2;" : "=f"(lo), "=f"(hi) : "l"(v));
    return make_float2(lo, hi);
}

__device__ __forceinline__ float sigf(float x)   { return __fdividef(1.f, 1.f + __expf(-x)); }
__device__ __forceinline__ float tanh_f(float x) { return 1.f - __fdividef(2.f, 1.f + __expf(2.f * x)); }

// acc[j][g][p]: j = unit half (tu, tu+100), g = gate (i,f,g,o), p = row-pair (2 rows each)
__device__ __forceinline__ void acc_init2(u64 acc[2][4][2], const float* __restrict__ vb_, int tu)
{
    const ulonglong2* b = reinterpret_cast<const ulonglong2*>(vb_) + tu * 4;
    ulonglong2 c0 = b[0], c1 = b[1], c2 = b[2], c3 = b[3];
#pragma unroll
    for (int p = 0; p < 2; p++) {
        acc[0][0][p] = c0.x; acc[0][1][p] = c0.y;
        acc[0][2][p] = c1.x; acc[0][3][p] = c1.y;
        acc[1][0][p] = c2.x; acc[1][1][p] = c2.y;
        acc[1][2][p] = c3.x; acc[1][3][p] = c3.y;
    }
}

__device__ __forceinline__ void fma_block(u64 acc[2][4][2], ulonglong2 c0, ulonglong2 c1,
                                          ulonglong2 c2, ulonglong2 c3, u64 p0, u64 p1)
{
    fma2(acc[0][0][0], c0.x, p0); fma2(acc[0][0][1], c0.x, p1);
    fma2(acc[0][1][0], c0.y, p0); fma2(acc[0][1][1], c0.y, p1);
    fma2(acc[0][2][0], c1.x, p0); fma2(acc[0][2][1], c1.x, p1);
    fma2(acc[0][3][0], c1.y, p0); fma2(acc[0][3][1], c1.y, p1);
    fma2(acc[1][0][0], c2.x, p0); fma2(acc[1][0][1], c2.x, p1);
    fma2(acc[1][1][0], c2.y, p0); fma2(acc[1][1][1], c2.y, p1);
    fma2(acc[1][2][0], c3.x, p0); fma2(acc[1][2][1], c3.x, p1);
    fma2(acc[1][3][0], c3.y, p0); fma2(acc[1][3][1], c3.y, p1);
}

__device__ __forceinline__ void acc_rank1_2(u64 acc[2][4][2], const float* __restrict__ wx,
                                            int tu, u64 p0, u64 p1)
{
    const ulonglong2* b = reinterpret_cast<const ulonglong2*>(wx) + tu * 4;
    fma_block(acc, b[0], b[1], b[2], b[3], p0, p1);
}

// gates += h @ W^T; W dup'd [k][tu][16], h in smem [u][row28] -> read as [k][row28].
__device__ __forceinline__ void gemm_pass2(const float* __restrict__ W, const float* __restrict__ hs,
                                           int tu, int ty, u64 acc[2][4][2])
{
    const ulonglong2* __restrict__ w2 = reinterpret_cast<const ulonglong2*>(W) + tu * 4;
    const float4*     __restrict__ h4 = reinterpret_cast<const float4*>(hs) + ty;
#pragma unroll 4
    for (int k = 0; k < HID; k++) {
        ulonglong2 c0 = w2[k * 400 + 0];
        ulonglong2 c1 = w2[k * 400 + 1];
        ulonglong2 c2 = w2[k * 400 + 2];
        ulonglong2 c3 = w2[k * 400 + 3];
        float4 hv = h4[k * 7];                 // 4 rows of h[k]
        u64 p0 = pair_of(hv.x, hv.y);          // register aliasing, no real MOV
        u64 p1 = pair_of(hv.z, hv.w);
        fma_block(acc, c0, c1, c2, c3, p0, p1);
    }
}

// c-state: u64 row-pairs, cs[u*14 + ty*2 + p]. h written back as [u][row28] floats.
__device__ __forceinline__ void cell_epi2(u64 acc[2][4][2], float* __restrict__ cs,
                                          float* __restrict__ hdst, int tu, int ty)
{
    u64* cb = reinterpret_cast<u64*>(cs);
#pragma unroll
    for (int j = 0; j < 2; j++) {
        int u = tu + j * 100;
        float hrow[4];
#pragma unroll
        for (int p = 0; p < 2; p++) {
            float2 iv = unpk(acc[j][0][p]);
            float2 fv = unpk(acc[j][1][p]);
            float2 gv = unpk(acc[j][2][p]);
            float2 ov = unpk(acc[j][3][p]);
            u64* cp = cb + u * 14 + ty * 2 + p;
            float2 cv = unpk(*cp);
            float cx = sigf(fv.x) * cv.x + sigf(iv.x) * tanh_f(gv.x);
            float cy = sigf(fv.y) * cv.y + sigf(iv.y) * tanh_f(gv.y);
            *cp = pair_of(cx, cy);
            hrow[p * 2]     = sigf(ov.x) * tanh_f(cx);
            hrow[p * 2 + 1] = sigf(ov.y) * tanh_f(cy);
        }
        *reinterpret_cast<float4*>(hdst + u * 28 + ty * 4) =
            make_float4(hrow[0], hrow[1], hrow[2], hrow[3]);
    }
}

// smem (floats): h0 5600 | h1 5600 | c0 5600 | c1 5600 | xs 3584 | vb 9600 |
//                lin 200 | inp 32 | part 224  = 36040 floats (144,160 B)
#define SMEM_FLOATS 36040

__global__ void __launch_bounds__(NTHR, 1)
lstm_kernel(const float* __restrict__ x, const float* __restrict__ linW,
            const float* __restrict__ linb, float* __restrict__ out)
{
    extern __shared__ float sm[];
    float* h0    = sm;            // [u=200][row=28]
    float* h1    = sm + 5600;
    float* c0s   = sm + 11200;    // u64 pairs [u][14]
    float* c1s   = sm + 16800;
    float* xs    = sm + 22400;    // [t=128][row=28]
    float* vb    = sm + 25984;    // 6 x 1600 dup'd
    float* lin_s = sm + 35584;    // 200
    float* inp_s = sm + 35784;    // 28 (+pad)
    float* part  = sm + 35816;    // 8 x 28 head partials

    const int tid  = threadIdx.x;
    const int ty   = tid % 7;     // row-block of 4 rows
    const int tu   = tid / 7;     // unit-pair 0..99 (units tu, tu+100)
    const int row0 = blockIdx.x * MCTA;

    // stage / init
    for (int i = tid; i < 22400; i += NTHR) sm[i] = 0.f;       // h0,h1,c0,c1
    for (int i = tid; i < TLEN * MCTA; i += NTHR) {
        int t = i / MCTA, r = i - t * MCTA;
        int grow = row0 + r;
        xs[i] = (grow < BATCH) ? x[grow * TLEN + t] : 0.f;
    }
    {
        const float* gv = &g_v[0][0];
        for (int i = tid; i < 6 * WROW; i += NTHR) vb[i] = gv[i];
    }
    for (int i = tid; i < HID; i += NTHR) lin_s[i] = linW[i];
    __syncthreads();

    const float* wx0  = vb;
    const float* b0   = vb + 1600;
    const float* b1   = vb + 3200;
    const float* dwx0 = vb + 4800;
    const float* db0  = vb + 6400;
    const float* db1  = vb + 8000;

    // ---------------- encoder: 128 steps ----------------
    for (int t = 0; t < TLEN; t++) {
        u64 acc[2][4][2];
        acc_init2(acc, b0, tu);
        {
            float4 xv = *reinterpret_cast<const float4*>(xs + t * MCTA + ty * 4);
            acc_rank1_2(acc, wx0, tu, pair_of(xv.x, xv.y), pair_of(xv.z, xv.w));
        }
        gemm_pass2(g_W[0], h0, tu, ty, acc);
        __syncthreads();
        cell_epi2(acc, c0s, h0, tu, ty);
        __syncthreads();

        u64 accb[2][4][2];
        acc_init2(accb, b1, tu);
        gemm_pass2(g_W[1], h0, tu, ty, accb);
        gemm_pass2(g_W[2], h1, tu, ty, accb);
        __syncthreads();
        cell_epi2(accb, c1s, h1, tu, ty);
        __syncthreads();
    }

    // decoder initial input = x[:, T-1]
    if (tid < MCTA) inp_s[tid] = xs[(TLEN - 1) * MCTA + tid];
    __syncthreads();

    const float lb = linb[0];

    // ---------------- decoder: 64 steps ----------------
    for (int t = 0; t < OUTLEN; t++) {
        u64 acc[2][4][2];
        acc_init2(acc, db0, tu);
        {
            float4 xv = *reinterpret_cast<const float4*>(inp_s + ty * 4);
            acc_rank1_2(acc, dwx0, tu, pair_of(xv.x, xv.y), pair_of(xv.z, xv.w));
        }
        gemm_pass2(g_W[3], h0, tu, ty, acc);
        __syncthreads();
        cell_epi2(acc, c0s, h0, tu, ty);
        __syncthreads();

        u64 accb[2][4][2];
        acc_init2(accb, db1, tu);
        gemm_pass2(g_W[4], h0, tu, ty, accb);   // input = new h0
        gemm_pass2(g_W[5], h1, tu, ty, accb);
        __syncthreads();
        cell_epi2(accb, c1s, h1, tu, ty);
        __syncthreads();

        // linear head: pred = h1 @ lin_W.T + lin_b (8 partial groups x 28 rows)
        if (tid < 224) {
            int grp = tid / MCTA, r = tid - grp * MCTA;
            int ub = grp * 25;
            float s = 0.f;
#pragma unroll 5
            for (int u = 0; u < 25; u++) s += lin_s[ub + u] * h1[(ub + u) * MCTA + r];
            part[grp * MCTA + r] = s;
        }
        __syncthreads();
        if (tid < MCTA) {
            float s = lb;
#pragma unroll
            for (int g = 0; g < 8; g++) s += part[g * MCTA + tid];
            if (row0 + tid < BATCH) out[(row0 + tid) * OUTLEN + t] = s;
            inp_s[tid] = s;
        }
        __syncthreads();
    }
}

extern "C" void kernel_launch(void* const* d_in, const int* in_sizes, int n_in,
                              void* d_out, int out_size)
{
    (void)in_sizes; (void)n_in; (void)out_size;
    const float* x     = (const float*)d_in[0];
    const float* eWih0 = (const float*)d_in[1];
    const float* eWhh0 = (const float*)d_in[2];
    const float* eb0   = (const float*)d_in[3];
    const float* eWih1 = (const float*)d_in[4];
    const float* eWhh1 = (const float*)d_in[5];
    const float* eb1   = (const float*)d_in[6];
    const float* dWih0 = (const float*)d_in[7];
    const float* dWhh0 = (const float*)d_in[8];
    const float* db0   = (const float*)d_in[9];
    const float* dWih1 = (const float*)d_in[10];
    const float* dWhh1 = (const float*)d_in[11];
    const float* db1   = (const float*)d_in[12];
    const float* linW  = (const float*)d_in[13];
    const float* linb  = (const float*)d_in[14];
    float* out = (float*)d_out;

    cudaFuncSetAttribute(lstm_kernel, cudaFuncAttributeMaxDynamicSharedMemorySize,
                         SMEM_FLOATS * (int)sizeof(float));

    prep_kernel<<<(WSZ + 255) / 256, 256>>>(eWhh0, eWih1, eWhh1, dWhh0, dWih1, dWhh1,
                                            eWih0, eb0, eb1, dWih0, db0, db1);
    lstm_kernel<<<NBLK, NTHR, SMEM_FLOATS * (int)sizeof(float)>>>(x, linW, linb, out);
}